// round 2
// baseline (speedup 1.0000x reference)
#include <cuda_runtime.h>
#include <math.h>

#define ANG   7
#define NV    49
#define HH    256
#define WW    256
#define BB    4
#define CROPP 8
#define CH    (HH - 2*CROPP)   // 240
#define CW    (WW - 2*CROPP)   // 240
#define HW3   (HH*WW*3)        // 196608
#define VIEW_STRIDE HW3
#define BATCH_STRIDE (NV*HW3)

__device__ double g_cl_sum;
__device__ double g_lx_sum;
__device__ double g_ly_sum;

__global__ void zero_acc_kernel() {
    g_cl_sum = 0.0; g_lx_sum = 0.0; g_ly_sum = 0.0;
}

// ---------------------------------------------------------------------------
// Color-loss kernel: one thread per cropped pixel (b, py, px).
// Computes cl[n] for 49 views via bilinear warp, angular 3x3 gaussian,
// top-m (m = floor(y)+1) extraction by gauss key, masked sum.
// ---------------------------------------------------------------------------
__global__ __launch_bounds__(128)
void color_kernel(const float* __restrict__ pred,
                  const float* __restrict__ x,
                  const float* __restrict__ y,
                  const int*   __restrict__ epoch)
{
    const int idx = blockIdx.x * 128 + threadIdx.x;   // 0 .. 230399 (exact grid)
    const int px  = (idx % CW) + CROPP;
    const int py  = ((idx / CW) % CH) + CROPP;
    const int b   = idx / (CH * CW);

    const float p = pred[(b * HH + py) * WW + px];
    const float* xb = x + (size_t)b * BATCH_STRIDE;

    // Per-offset (du / dv share the same 7 offsets) coordinate precompute
    int   yo0[7], yo1[7], xo0[7], xo1[7];
    float ta[7], tb[7];
#pragma unroll
    for (int k = 0; k < 7; ++k) {
        const float off = (float)(k - 3);
        float cy = fminf(fmaxf((float)py + p * off, 0.0f), (float)(HH - 1));
        float fy = floorf(cy);
        int   y0 = (int)fy;
        ta[k]  = cy - fy;
        yo0[k] = y0 * (WW * 3);
        yo1[k] = min(y0 + 1, HH - 1) * (WW * 3);

        float cx = fminf(fmaxf((float)px + p * off, 0.0f), (float)(WW - 1));
        float fx = floorf(cx);
        int   x0 = (int)fx;
        tb[k]  = cx - fx;
        xo0[k] = x0 * 3;
        xo1[k] = min(x0 + 1, WW - 1) * 3;
    }

    // Center view pixel (view 24 warps to identity at its own pixel)
    const int cen_off = 24 * VIEW_STRIDE + py * (WW * 3) + px * 3;
    const float cen0 = xb[cen_off + 0];
    const float cen1 = xb[cen_off + 1];
    const float cen2 = xb[cen_off + 2];

    float cl[NV];
    float total = 0.0f;
#pragma unroll
    for (int n = 0; n < NV; ++n) {
        const int du = n / 7, dv = n % 7;
        const float* base = xb + n * VIEW_STRIDE;
        const float* p00 = base + yo0[du] + xo0[dv];
        const float* p01 = base + yo0[du] + xo1[dv];
        const float* p10 = base + yo1[du] + xo0[dv];
        const float* p11 = base + yo1[du] + xo1[dv];
        const float ty = ta[du], tx = tb[dv];
        const float w00 = (1.0f - ty) * (1.0f - tx);
        const float w01 = (1.0f - ty) * tx;
        const float w10 = ty * (1.0f - tx);
        const float w11 = ty * tx;

        float v0 = w00 * p00[0] + w01 * p01[0] + w10 * p10[0] + w11 * p11[0];
        float v1 = w00 * p00[1] + w01 * p01[1] + w10 * p10[1] + w11 * p11[1];
        float v2 = w00 * p00[2] + w01 * p01[2] + w10 * p10[2] + w11 * p11[2];

        float acc = fabsf(v0 - cen0) + fabsf(v1 - cen1) + fabsf(v2 - cen2);
        cl[n] = acc * (1.0f / 3.0f);
        total += cl[n];
    }

    // Sort key: angular 3x3 gaussian of cl (edge padded) when epoch > 0,
    // else cl itself.
    const int ep = epoch ? *epoch : 1;
    float key[NV];
    if (ep > 0) {
        const float G00 = 0.0751f, G01 = 0.1238f, G11 = 0.2042f;
#pragma unroll
        for (int u = 0; u < 7; ++u) {
#pragma unroll
            for (int v = 0; v < 7; ++v) {
                float s = 0.0f;
#pragma unroll
                for (int i = -1; i <= 1; ++i) {
#pragma unroll
                    for (int j = -1; j <= 1; ++j) {
                        const int uu = min(max(u + i, 0), 6);
                        const int vv = min(max(v + j, 0), 6);
                        const float g = (i == 0 && j == 0) ? G11
                                      : ((i == 0 || j == 0) ? G01 : G00);
                        s += g * cl[uu * 7 + vv];
                    }
                }
                key[u * 7 + v] = s;
            }
        }
    } else {
#pragma unroll
        for (int n = 0; n < NV; ++n) key[n] = cl[n];
    }

    // mask[n] = (rank n > y) * N/(N-y); ranks in descending key order.
    // => contribution = (total - sum of cl over the m largest keys) * N/(N-y),
    //    m = floor(y)+1.
    const float yv = y[(b * HH + py) * WW + px];
    int m = (int)floorf(yv) + 1;
    if (m > NV) m = NV;
    if (m < 0)  m = 0;

    float thr = INFINITY;
    float topsum = 0.0f;
    for (int k = 0; k < m; ++k) {
        float bestk = -INFINITY;
        float bestc = 0.0f;
#pragma unroll
        for (int n = 0; n < NV; ++n) {
            bool better = (key[n] < thr) && (key[n] > bestk);
            if (better) { bestk = key[n]; bestc = cl[n]; }
        }
        topsum += bestc;
        thr = bestk;
    }

    float contrib = (total - topsum) * ((float)NV / ((float)NV - yv));

    // Block reduction -> one double atomic per block
#pragma unroll
    for (int o = 16; o > 0; o >>= 1)
        contrib += __shfl_down_sync(0xFFFFFFFFu, contrib, o);
    __shared__ float ws[4];
    const int lane = threadIdx.x & 31;
    const int wid  = threadIdx.x >> 5;
    if (lane == 0) ws[wid] = contrib;
    __syncthreads();
    if (threadIdx.x == 0) {
        float s = ws[0] + ws[1] + ws[2] + ws[3];
        atomicAdd(&g_cl_sum, (double)s);
    }
}

// ---------------------------------------------------------------------------
// Edge-aware smoothness kernel: lx and ly sums over cropped regions.
// One thread per (b, ry, cx) in 240x240; lx valid when cx < 239, ly when ry < 239.
// ---------------------------------------------------------------------------
__global__ __launch_bounds__(128)
void grad_kernel(const float* __restrict__ pred,
                 const float* __restrict__ x)
{
    const int idx = blockIdx.x * 128 + threadIdx.x;
    const int cx = idx % CW;
    const int ry = (idx / CW) % CH;
    const int b  = idx / (CH * CW);
    const int px = cx + CROPP;
    const int py = ry + CROPP;

    const float* I  = x + (size_t)b * BATCH_STRIDE + 24 * VIEW_STRIDE;
    const float* pr = pred + b * HH * WW;

    float tx = 0.0f, tyv = 0.0f;
    const int o = py * (WW * 3) + px * 3;

    if (cx < CW - 1) {  // xx' in [8, 246]
        float a = fabsf(I[o + 3] - I[o + 0])
                + fabsf(I[o + 4] - I[o + 1])
                + fabsf(I[o + 5] - I[o + 2]);
        float wx = expf(-150.0f * a * (1.0f / 3.0f));
        float dg = pr[py * WW + px + 1] - pr[py * WW + px];
        tx = wx * fabsf(dg);
    }
    if (ry < CH - 1) {  // yy' in [8, 246]
        float a = fabsf(I[o + WW * 3 + 0] - I[o + 0])
                + fabsf(I[o + WW * 3 + 1] - I[o + 1])
                + fabsf(I[o + WW * 3 + 2] - I[o + 2]);
        float wy = expf(-150.0f * a * (1.0f / 3.0f));
        float dg = pr[(py + 1) * WW + px] - pr[py * WW + px];
        tyv = wy * fabsf(dg);
    }

#pragma unroll
    for (int off = 16; off > 0; off >>= 1) {
        tx  += __shfl_down_sync(0xFFFFFFFFu, tx, off);
        tyv += __shfl_down_sync(0xFFFFFFFFu, tyv, off);
    }
    __shared__ float wsx[4], wsy[4];
    const int lane = threadIdx.x & 31;
    const int wid  = threadIdx.x >> 5;
    if (lane == 0) { wsx[wid] = tx; wsy[wid] = tyv; }
    __syncthreads();
    if (threadIdx.x == 0) {
        atomicAdd(&g_lx_sum, (double)(wsx[0] + wsx[1] + wsx[2] + wsx[3]));
        atomicAdd(&g_ly_sum, (double)(wsy[0] + wsy[1] + wsy[2] + wsy[3]));
    }
}

__global__ void finalize_kernel(float* __restrict__ out)
{
    const double cl_mean = g_cl_sum / (double)((size_t)BB * NV * CH * CW);
    const double lx = g_lx_sum / (double)(BB * CH * (CW - 1));
    const double ly = g_ly_sum / (double)(BB * (CH - 1) * CW);
    out[0] = (float)(cl_mean + 0.1 * 0.5 * (lx + ly));
}

extern "C" void kernel_launch(void* const* d_in, const int* in_sizes, int n_in,
                              void* d_out, int out_size)
{
    const float* pred  = (const float*)d_in[0];
    const float* x     = (const float*)d_in[1];
    const float* y     = (const float*)d_in[2];
    const int*   epoch = (n_in > 3) ? (const int*)d_in[3] : nullptr;
    float* out = (float*)d_out;

    const int npix   = BB * CH * CW;          // 230400
    const int blocks = npix / 128;            // 1800, exact

    zero_acc_kernel<<<1, 1>>>();
    color_kernel<<<blocks, 128>>>(pred, x, y, epoch);
    grad_kernel<<<blocks, 128>>>(pred, x);
    finalize_kernel<<<1, 1>>>(out);
}